// round 1
// baseline (speedup 1.0000x reference)
#include <cuda_runtime.h>
#include <math.h>

#define GDIM 128
#define G3 (GDIM*GDIM*GDIM)
#define NPART 4096
#define NEMO 4

// Precomputed particle data (scratch; __device__ globals, no allocation)
__device__ float4 g_part[NPART * 2];   // [2p]=(gp0,gp1,gp2,omega) [2p+1]=(em0..em3)
__device__ int    g_pc[NPART];         // packed floor cell: c0 | c1<<8 | c2<<16

__global__ void prep_kernel(const float* __restrict__ pos,
                            const float* __restrict__ inten,
                            const float* __restrict__ emo) {
    int p = blockIdx.x * blockDim.x + threadIdx.x;
    if (p >= NPART) return;
    float gp0 = (pos[3*p+0] + 1.0f) * 63.5f;
    float gp1 = (pos[3*p+1] + 1.0f) * 63.5f;
    float gp2 = (pos[3*p+2] + 1.0f) * 63.5f;
    int c0 = min(max((int)floorf(gp0), 0), GDIM-1);
    int c1 = min(max((int)floorf(gp1), 0), GDIM-1);
    int c2 = min(max((int)floorf(gp2), 0), GDIM-1);
    g_pc[p] = c0 | (c1 << 8) | (c2 << 16);
    g_part[2*p+0] = make_float4(gp0, gp1, gp2, inten[p] * 0.01f);
    g_part[2*p+1] = make_float4(emo[4*p+0], emo[4*p+1], emo[4*p+2], emo[4*p+3]);
}

// One warp per sample point. Each lane owns 2 of the 64 cells of the 4x4x4
// block (cells lane and lane+32; cell index = l0*16 + l1*4 + l2, axis0 major).
__global__ void __launch_bounds__(256)
main_kernel(const float* __restrict__ spos,
            const float* __restrict__ H0,
            const float* __restrict__ E0,
            float* __restrict__ out) {
    __shared__ float sv[8][5][64];
    const unsigned FULL = 0xffffffffu;
    const int wib  = threadIdx.x >> 5;
    const int lane = threadIdx.x & 31;
    const int s    = (blockIdx.x << 3) + wib;   // sample index, 0..8191

    const float px = spos[3*s+0];
    const float py = spos[3*s+1];
    const float pz = spos[3*s+2];
    // grid axis0 <- sample comp2 (z), axis1 <- comp1 (y), axis2 <- comp0 (x)
    float t0 = fminf(fmaxf((pz + 1.0f) * 63.5f, 0.0f), 127.0f);
    float t1 = fminf(fmaxf((py + 1.0f) * 63.5f, 0.0f), 127.0f);
    float t2 = fminf(fmaxf((px + 1.0f) * 63.5f, 0.0f), 127.0f);
    int i0 = (int)floorf(t0); float f0 = t0 - (float)i0;
    int i1 = (int)floorf(t1); float f1 = t1 - (float)i1;
    int i2 = (int)floorf(t2); float f2 = t2 - (float)i2;

    int ga0[4], ga1[4], ga2[4];   // clamped global coords of block cells (edge padding)
#pragma unroll
    for (int l = 0; l < 4; l++) {
        ga0[l] = min(max(i0 - 1 + l, 0), 127);
        ga1[l] = min(max(i1 - 1 + l, 0), 127);
        ga2[l] = min(max(i2 - 1 + l, 0), 127);
    }

    const int l0 = lane >> 4;
    const int l1 = (lane >> 2) & 3;
    const int l2 = lane & 3;
    const int gAi = ga0[l0], gBi = ga0[l0 + 2];
    const int g1i = ga1[l1], g2i = ga2[l2];
    const float gAf = (float)gAi, gBf = (float)gBi;
    const float g1f = (float)g1i, g2f = (float)g2i;

    const int lo0 = ga0[0] - 9, hi0 = ga0[3] + 9;
    const int lo1 = ga1[0] - 9, hi1 = ga1[3] + 9;
    const int lo2 = ga2[0] - 9, hi2 = ga2[3] + 9;

    float aH0 = 0.f, aH1 = 0.f;
    float aE00 = 0.f, aE01 = 0.f, aE10 = 0.f, aE11 = 0.f;
    float aE20 = 0.f, aE21 = 0.f, aE30 = 0.f, aE31 = 0.f;

    for (int base = 0; base < NPART; base += 32) {
        const int pcv = g_pc[base + lane];
        const int c0 = pcv & 255, c1 = (pcv >> 8) & 255, c2 = (pcv >> 16) & 255;
        const bool hit = (c0 >= lo0) & (c0 <= hi0) &
                         (c1 >= lo1) & (c1 <= hi1) &
                         (c2 >= lo2) & (c2 <= hi2);
        unsigned msk = __ballot_sync(FULL, hit);
        while (msk) {
            const int j = __ffs(msk) - 1;
            msk &= msk - 1;
            const int pcj = __shfl_sync(FULL, pcv, j);
            const float4 A  = __ldg(&g_part[2*(base + j) + 0]);
            const float4 Em = __ldg(&g_part[2*(base + j) + 1]);
            const int pc0 = pcj & 255, pc1 = (pcj >> 8) & 255, pc2 = (pcj >> 16) & 255;

            const float d1 = g1f - A.y, d2 = g2f - A.z;
            const float s12 = d1*d1 + d2*d2;
            const bool in12 = ((unsigned)(g1i - pc1 + 9) <= 18u) &
                              ((unsigned)(g2i - pc2 + 9) <= 18u);
            const float dA = gAf - A.x;
            const float dB = gBf - A.x;
            const bool inA = in12 & ((unsigned)(gAi - pc0 + 9) <= 18u);
            const bool inB = in12 & ((unsigned)(gBi - pc0 + 9) <= 18u);
            const float eA = __expf(-(s12 + dA*dA) * 0.048828125f);
            const float eB = __expf(-(s12 + dB*dB) * 0.048828125f);
            const float wA = inA ? A.w * eA : 0.0f;
            const float wB = inB ? A.w * eB : 0.0f;
            aH0 += wA;          aH1 += wB;
            aE00 += wA * Em.x;  aE01 += wB * Em.x;
            aE10 += wA * Em.y;  aE11 += wB * Em.y;
            aE20 += wA * Em.z;  aE21 += wB * Em.z;
            aE30 += wA * Em.w;  aE31 += wB * Em.w;
        }
    }

    // Add base grid values (H0 / E0) and stash the 4x4x4 block in shared.
    const int fA = (gAi * GDIM + g1i) * GDIM + g2i;
    const int fB = (gBi * GDIM + g1i) * GDIM + g2i;
    sv[wib][0][lane]      = aH0  + __ldg(&H0[fA]);
    sv[wib][0][lane + 32] = aH1  + __ldg(&H0[fB]);
    sv[wib][1][lane]      = aE00 + __ldg(&E0[0*G3 + fA]);
    sv[wib][1][lane + 32] = aE01 + __ldg(&E0[0*G3 + fB]);
    sv[wib][2][lane]      = aE10 + __ldg(&E0[1*G3 + fA]);
    sv[wib][2][lane + 32] = aE11 + __ldg(&E0[1*G3 + fB]);
    sv[wib][3][lane]      = aE20 + __ldg(&E0[2*G3 + fA]);
    sv[wib][3][lane + 32] = aE21 + __ldg(&E0[2*G3 + fB]);
    sv[wib][4][lane]      = aE30 + __ldg(&E0[3*G3 + fA]);
    sv[wib][4][lane + 32] = aE31 + __ldg(&E0[3*G3 + fB]);
    __syncwarp();

    // 8 corners on lanes 0..7: diffusion step + ReLU + trilinear weight,
    // reduce across 8 lanes, lane 0 writes.
#pragma unroll
    for (int ch = 0; ch < 5; ch++) {
        float part = 0.0f;
        if (lane < 8) {
            const int d0 = (lane >> 2) & 1, d1c = (lane >> 1) & 1, d2c = lane & 1;
            const int ci = (1 + d0) * 16 + (1 + d1c) * 4 + (1 + d2c);
            const float* v = sv[wib][ch];
            const float c = v[ci];
            const float lap = v[ci-16] + v[ci+16] + v[ci-4] + v[ci+4]
                            + v[ci-1]  + v[ci+1]  - 6.0f * c;
            float val;
            if (ch == 0) val = c * (1.0f - 5e-5f) + 0.002f * lap;
            else         val = c * (1.0f - 5e-5f) + 5e-5f + 0.001f * lap;
            val = fmaxf(val, 0.0f);
            const float w = (d0  ? f0 : 1.0f - f0)
                          * (d1c ? f1 : 1.0f - f1)
                          * (d2c ? f2 : 1.0f - f2);
            part = val * w;
        }
        part += __shfl_down_sync(FULL, part, 4);
        part += __shfl_down_sync(FULL, part, 2);
        part += __shfl_down_sync(FULL, part, 1);
        if (lane == 0) out[s * 5 + ch] = part;
    }
}

extern "C" void kernel_launch(void* const* d_in, const int* in_sizes, int n_in,
                              void* d_out, int out_size) {
    const float* positions   = (const float*)d_in[0];  // (4096,3)
    const float* intensities = (const float*)d_in[1];  // (4096,)
    const float* emotions    = (const float*)d_in[2];  // (4096,4)
    const float* sample_pos  = (const float*)d_in[3];  // (8,1024,3)
    const float* H0          = (const float*)d_in[4];  // (128,128,128)
    const float* E0          = (const float*)d_in[5];  // (4,128,128,128)
    float* out = (float*)d_out;                        // (8,1024,5)

    prep_kernel<<<(NPART + 255) / 256, 256>>>(positions, intensities, emotions);
    main_kernel<<<1024, 256>>>(sample_pos, H0, E0, out);
    (void)in_sizes; (void)n_in; (void)out_size;
}

// round 2
// speedup vs baseline: 1.6555x; 1.6555x over previous
#include <cuda_runtime.h>
#include <math.h>

#define GDIM 128
#define G3 (GDIM*GDIM*GDIM)
#define NPART 4096
#define NBIN 64            // bins of width 2 on grid axis 0

// Sorted particle data (scratch; __device__ globals, no allocation)
__device__ float4 g_ps[NPART * 2];     // [2p]=(gp0,gp1,gp2,omega) [2p+1]=(em0..3)
__device__ int    g_pcs[NPART + 32];   // packed floor cell, +32 pad sentinels
__device__ int    g_binstart[NBIN + 1];

// ---------------------------------------------------------------------------
// Fused prep + deterministic stable counting sort by bin = c0>>1.
// Single block, 1024 threads = 32 warps; warp w owns chunks 4w..4w+3,
// chunk c = particles [32c, 32c+32).
// ---------------------------------------------------------------------------
__global__ void __launch_bounds__(1024)
sort_kernel(const float* __restrict__ pos,
            const float* __restrict__ inten,
            const float* __restrict__ emo) {
    __shared__ int cnt[128][NBIN];       // per-chunk per-bin counts -> prefixes
    __shared__ int bstart[NBIN + 1];
    const int tid = threadIdx.x;
    const int w   = tid >> 5;
    const int lane = tid & 31;

    for (int i = tid; i < 128 * NBIN; i += 1024) ((int*)cnt)[i] = 0;
    __syncthreads();

    int    mypc[4], mybin[4], myrank[4];
    float4 mypA[4], mypE[4];
#pragma unroll
    for (int k = 0; k < 4; k++) {
        const int c = w * 4 + k;
        const int i = c * 32 + lane;
        const float gp0 = (pos[3*i+0] + 1.0f) * 63.5f;
        const float gp1 = (pos[3*i+1] + 1.0f) * 63.5f;
        const float gp2 = (pos[3*i+2] + 1.0f) * 63.5f;
        const int c0 = min(max((int)floorf(gp0), 0), GDIM-1);
        const int c1 = min(max((int)floorf(gp1), 0), GDIM-1);
        const int c2 = min(max((int)floorf(gp2), 0), GDIM-1);
        mypc[k] = c0 | (c1 << 8) | (c2 << 16);
        const int b = c0 >> 1;
        const unsigned m = __match_any_sync(0xffffffffu, b);
        const int r = __popc(m & ((1u << lane) - 1u));
        if (r == 0) cnt[c][b] = __popc(m);
        mybin[k]  = b;
        myrank[k] = r;
        mypA[k] = make_float4(gp0, gp1, gp2, inten[i] * 0.01f);
        mypE[k] = make_float4(emo[4*i+0], emo[4*i+1], emo[4*i+2], emo[4*i+3]);
    }
    __syncthreads();

    // Column-wise exclusive prefix over chunks (thread t owns bin t).
    if (tid < NBIN) {
        int s = 0;
#pragma unroll 4
        for (int c = 0; c < 128; c++) { const int v = cnt[c][tid]; cnt[c][tid] = s; s += v; }
        bstart[tid] = s;   // temporarily: bin totals
    }
    __syncthreads();
    if (tid == 0) {
        int s = 0;
#pragma unroll
        for (int b = 0; b < NBIN; b++) { const int t = bstart[b]; bstart[b] = s; s += t; }
        bstart[NBIN] = s;
    }
    __syncthreads();

#pragma unroll
    for (int k = 0; k < 4; k++) {
        const int c = w * 4 + k;
        const int p = bstart[mybin[k]] + cnt[c][mybin[k]] + myrank[k];
        g_pcs[p]        = mypc[k];
        g_ps[2*p + 0]   = mypA[k];
        g_ps[2*p + 1]   = mypE[k];
    }
    if (tid <= NBIN) g_binstart[tid] = bstart[tid];
    if (tid < 32)    g_pcs[NPART + tid] = 0x0000FF00;   // c1=255: fails every window
}

// ---------------------------------------------------------------------------
// One warp per sample. Each lane owns ONE of the 32 cells actually needed:
// 8 trilinear corners (block coords in {1,2}^3) + their 24 face neighbors.
// ---------------------------------------------------------------------------
__global__ void __launch_bounds__(256)
main_kernel(const float* __restrict__ spos,
            const float* __restrict__ H0,
            const float* __restrict__ E0,
            float* __restrict__ out) {
    __shared__ float sv[8][5][64];
    const unsigned FULL = 0xffffffffu;
    const int wib  = threadIdx.x >> 5;
    const int lane = threadIdx.x & 31;
    const int s    = (blockIdx.x << 3) + wib;

    const float px = spos[3*s+0];
    const float py = spos[3*s+1];
    const float pz = spos[3*s+2];
    // grid axis0 <- comp2, axis1 <- comp1, axis2 <- comp0 (reference transpose)
    const float t0 = fminf(fmaxf((pz + 1.0f) * 63.5f, 0.0f), 127.0f);
    const float t1 = fminf(fmaxf((py + 1.0f) * 63.5f, 0.0f), 127.0f);
    const float t2 = fminf(fmaxf((px + 1.0f) * 63.5f, 0.0f), 127.0f);
    const int i0 = (int)floorf(t0); const float f0 = t0 - (float)i0;
    const int i1 = (int)floorf(t1); const float f1 = t1 - (float)i1;
    const int i2 = (int)floorf(t2); const float f2 = t2 - (float)i2;

    // lane -> block coords (b0,b1,b2), covering the 32 needed cells
    int b0, b1, b2;
    if (lane < 8) {
        b0 = 1 + ((lane >> 2) & 1); b1 = 1 + ((lane >> 1) & 1); b2 = 1 + (lane & 1);
    } else {
        const int idx = lane - 8, axis = idx >> 3, rest = idx & 7;
        const int s3 = ((rest >> 2) & 1) * 3;
        const int u = 1 + ((rest >> 1) & 1), v = 1 + (rest & 1);
        b0 = (axis == 0) ? s3 : u;
        b1 = (axis == 1) ? s3 : ((axis == 0) ? u : v);
        b2 = (axis == 2) ? s3 : v;
    }
    const int gc0 = min(max(i0 - 1 + b0, 0), 127);
    const int gc1 = min(max(i1 - 1 + b1, 0), 127);
    const int gc2 = min(max(i2 - 1 + b2, 0), 127);
    const float gcf0 = (float)gc0, gcf1 = (float)gc1, gcf2 = (float)gc2;

    // particle-window (covers all 32 cells)
    const int lo0 = min(max(i0 - 1, 0), 127) - 9, hi0 = min(max(i0 + 2, 0), 127) + 9;
    const int lo1 = min(max(i1 - 1, 0), 127) - 9, hi1 = min(max(i1 + 2, 0), 127) + 9;
    const int lo2 = min(max(i2 - 1, 0), 127) - 9, hi2 = min(max(i2 + 2, 0), 127) + 9;
    const unsigned sp0 = (unsigned)(hi0 - lo0);
    const unsigned sp1 = (unsigned)(hi1 - lo1);
    const unsigned sp2 = (unsigned)(hi2 - lo2);

    // contiguous candidate segment from the c0-sorted order
    const int binlo = max(lo0, 0) >> 1;
    const int binhi = min(hi0, 127) >> 1;
    const int j0 = g_binstart[binlo];
    const int j1 = g_binstart[binhi + 1];

    float aH = 0.f, aE0 = 0.f, aE1 = 0.f, aE2 = 0.f, aE3 = 0.f;

    for (int base = j0 & ~31; base < j1; base += 32) {
        const int pcv = g_pcs[base + lane];
        const int c0 = pcv & 255, c1 = (pcv >> 8) & 255, c2 = (pcv >> 16) & 255;
        const bool hit = ((unsigned)(c0 - lo0) <= sp0) &
                         ((unsigned)(c1 - lo1) <= sp1) &
                         ((unsigned)(c2 - lo2) <= sp2);
        unsigned msk = __ballot_sync(FULL, hit);
        while (msk) {
            const int j = __ffs(msk) - 1;
            msk &= msk - 1;
            const int pcj = __shfl_sync(FULL, pcv, j);
            const float4 A  = __ldg(&g_ps[2*(base + j) + 0]);
            const float4 Em = __ldg(&g_ps[2*(base + j) + 1]);
            const int pc0 = pcj & 255, pc1 = (pcj >> 8) & 255, pc2 = (pcj >> 16) & 255;
            const bool in = ((unsigned)(gc0 - pc0 + 9) <= 18u) &
                            ((unsigned)(gc1 - pc1 + 9) <= 18u) &
                            ((unsigned)(gc2 - pc2 + 9) <= 18u);
            const float d0 = gcf0 - A.x;
            const float d1 = gcf1 - A.y;
            const float d2 = gcf2 - A.z;
            const float e = __expf(-(d0*d0 + d1*d1 + d2*d2) * 0.048828125f);
            const float wv = in ? A.w * e : 0.0f;
            aH  += wv;
            aE0 += wv * Em.x;  aE1 += wv * Em.y;
            aE2 += wv * Em.z;  aE3 += wv * Em.w;
        }
    }

    // add base grid values, stash in shared (only the 32 needed slots)
    const int ci   = b0 * 16 + b1 * 4 + b2;
    const int flat = (gc0 * GDIM + gc1) * GDIM + gc2;
    sv[wib][0][ci] = aH  + __ldg(&H0[flat]);
    sv[wib][1][ci] = aE0 + __ldg(&E0[0*G3 + flat]);
    sv[wib][2][ci] = aE1 + __ldg(&E0[1*G3 + flat]);
    sv[wib][3][ci] = aE2 + __ldg(&E0[2*G3 + flat]);
    sv[wib][4][ci] = aE3 + __ldg(&E0[3*G3 + flat]);
    __syncwarp();

    // diffusion step + ReLU + trilinear reduce (8 corner lanes)
#pragma unroll
    for (int ch = 0; ch < 5; ch++) {
        float part = 0.0f;
        if (lane < 8) {
            const int d0 = (lane >> 2) & 1, d1c = (lane >> 1) & 1, d2c = lane & 1;
            const int cc = (1 + d0) * 16 + (1 + d1c) * 4 + (1 + d2c);
            const float* v = sv[wib][ch];
            const float c = v[cc];
            const float lap = v[cc-16] + v[cc+16] + v[cc-4] + v[cc+4]
                            + v[cc-1]  + v[cc+1]  - 6.0f * c;
            float val;
            if (ch == 0) val = c * (1.0f - 5e-5f) + 0.002f * lap;
            else         val = c * (1.0f - 5e-5f) + 5e-5f + 0.001f * lap;
            val = fmaxf(val, 0.0f);
            const float wq = (d0  ? f0 : 1.0f - f0)
                           * (d1c ? f1 : 1.0f - f1)
                           * (d2c ? f2 : 1.0f - f2);
            part = val * wq;
        }
        part += __shfl_down_sync(FULL, part, 4);
        part += __shfl_down_sync(FULL, part, 2);
        part += __shfl_down_sync(FULL, part, 1);
        if (lane == 0) out[s * 5 + ch] = part;
    }
}

extern "C" void kernel_launch(void* const* d_in, const int* in_sizes, int n_in,
                              void* d_out, int out_size) {
    const float* positions   = (const float*)d_in[0];  // (4096,3)
    const float* intensities = (const float*)d_in[1];  // (4096,)
    const float* emotions    = (const float*)d_in[2];  // (4096,4)
    const float* sample_pos  = (const float*)d_in[3];  // (8,1024,3)
    const float* H0          = (const float*)d_in[4];  // (128,128,128)
    const float* E0          = (const float*)d_in[5];  // (4,128,128,128)
    float* out = (float*)d_out;                        // (8,1024,5)

    sort_kernel<<<1, 1024>>>(positions, intensities, emotions);
    main_kernel<<<1024, 256>>>(sample_pos, H0, E0, out);
    (void)in_sizes; (void)n_in; (void)out_size;
}